// round 1
// baseline (speedup 1.0000x reference)
#include <cuda_runtime.h>
#include <cuda_bf16.h>

#define RES   256
#define RANK  12
#define OUTC  8

// Projected planes: [plane][texel][2 x float4] = 3 * 65536 * 32B = 6 MB scratch.
// Static __device__ array (allocation-free per harness rules), float4 for alignment.
__device__ float4 g_planes4[3][RES * RES * 2];

// ---------------------------------------------------------------------------
// Prolog: project each plane's 12 channels down to 8 via the matching slice of
// proj_w. Runs every replay (deterministic, graph-capturable).
//   g_planes[p][y][x][o] = sum_k plane_p[y][x][k] * W[o][p*12 + k]
// ---------------------------------------------------------------------------
__global__ void project_planes_kernel(const float* __restrict__ pxy,
                                      const float* __restrict__ pxz,
                                      const float* __restrict__ pyz,
                                      const float* __restrict__ W)
{
    const int p = blockIdx.y;
    const float* __restrict__ src = (p == 0) ? pxy : ((p == 1) ? pxz : pyz);

    __shared__ float w[OUTC][RANK];
    int t = threadIdx.x;
    if (t < OUTC * RANK) {
        int o = t / RANK;
        int k = t % RANK;
        w[o][k] = W[o * (3 * RANK) + p * RANK + k];
    }
    __syncthreads();

    int texel = blockIdx.x * blockDim.x + threadIdx.x;   // 0 .. 65535
    const float* __restrict__ in = src + (size_t)texel * RANK;

    float f[RANK];
    // 48B per texel, 16B-aligned: three float4 loads
    float4 i0 = __ldg((const float4*)(in));
    float4 i1 = __ldg((const float4*)(in + 4));
    float4 i2 = __ldg((const float4*)(in + 8));
    f[0]=i0.x; f[1]=i0.y; f[2]=i0.z; f[3]=i0.w;
    f[4]=i1.x; f[5]=i1.y; f[6]=i1.z; f[7]=i1.w;
    f[8]=i2.x; f[9]=i2.y; f[10]=i2.z; f[11]=i2.w;

    float o[OUTC];
    #pragma unroll
    for (int c = 0; c < OUTC; c++) {
        float s = 0.f;
        #pragma unroll
        for (int k = 0; k < RANK; k++) s = fmaf(f[k], w[c][k], s);
        o[c] = s;
    }

    float4* dst = &g_planes4[p][(size_t)texel * 2];
    dst[0] = make_float4(o[0], o[1], o[2], o[3]);
    dst[1] = make_float4(o[4], o[5], o[6], o[7]);
}

// ---------------------------------------------------------------------------
// Main: per point, 3 bilinear samples of the 8-channel projected planes,
// accumulate, add bias, clip, store.
// ---------------------------------------------------------------------------
__device__ __forceinline__ float4 f4lerp(float4 a, float4 b, float w) {
    return make_float4(fmaf(w, b.x - a.x, a.x),
                       fmaf(w, b.y - a.y, a.y),
                       fmaf(w, b.z - a.z, a.z),
                       fmaf(w, b.w - a.w, a.w));
}
__device__ __forceinline__ float4 f4add(float4 a, float4 b) {
    return make_float4(a.x + b.x, a.y + b.y, a.z + b.z, a.w + b.w);
}

__device__ __forceinline__ void sample_accum(const float4* __restrict__ plane,
                                             float cx, float cy,
                                             float4& acc0, float4& acc1)
{
    // unnormalize, align_corners=False, border clamp (subsumes coord clip)
    float ix = fminf(fmaxf(fmaf(cx, 128.f, 127.5f), 0.f), 255.f);
    float iy = fminf(fmaxf(fmaf(cy, 128.f, 127.5f), 0.f), 255.f);
    float x0f = floorf(ix);
    float y0f = floorf(iy);
    float wx = ix - x0f;
    float wy = iy - y0f;
    int x0 = (int)x0f;
    int y0 = (int)y0f;
    int dx = (x0 < RES - 1) ? 2       : 0;  // step in float4 units
    int dy = (y0 < RES - 1) ? RES * 2 : 0;

    const float4* b00 = plane + ((size_t)(y0 * RES + x0) * 2);
    float4 a0 = __ldg(b00);          float4 a1 = __ldg(b00 + 1);
    float4 b0 = __ldg(b00 + dx);     float4 b1 = __ldg(b00 + dx + 1);
    const float4* b10 = b00 + dy;
    float4 c0 = __ldg(b10);          float4 c1 = __ldg(b10 + 1);
    float4 d0 = __ldg(b10 + dx);     float4 d1 = __ldg(b10 + dx + 1);

    float4 top0 = f4lerp(a0, b0, wx);
    float4 top1 = f4lerp(a1, b1, wx);
    float4 bot0 = f4lerp(c0, d0, wx);
    float4 bot1 = f4lerp(c1, d1, wx);
    acc0 = f4add(acc0, f4lerp(top0, bot0, wy));
    acc1 = f4add(acc1, f4lerp(top1, bot1, wy));
}

__global__ void __launch_bounds__(256)
geo_encoder_kernel(const float* __restrict__ coords,
                   const float* __restrict__ proj_b,
                   float* __restrict__ out,
                   int N)
{
    int i = blockIdx.x * blockDim.x + threadIdx.x;
    if (i >= N) return;

    // Coalesced: warp reads 384 contiguous bytes
    float cx = coords[3 * (size_t)i + 0];
    float cy = coords[3 * (size_t)i + 1];
    float cz = coords[3 * (size_t)i + 2];
    // reference clips coords to [-1,1] first; ix/iy clamp subsumes this
    // (monotone map, clamp to [0,255] gives identical sample indices/weights)

    float4 acc0 = make_float4(0.f, 0.f, 0.f, 0.f);
    float4 acc1 = make_float4(0.f, 0.f, 0.f, 0.f);

    sample_accum(g_planes4[0], cx, cy, acc0, acc1);  // xy plane: x=c0(W), y=c1(H)
    sample_accum(g_planes4[1], cx, cz, acc0, acc1);  // xz plane: x=c0,   y=c2
    sample_accum(g_planes4[2], cy, cz, acc0, acc1);  // yz plane: x=c1,   y=c2

    float4 bias0 = __ldg((const float4*)proj_b);
    float4 bias1 = __ldg((const float4*)(proj_b + 4));

    float4 o0 = f4add(acc0, bias0);
    float4 o1 = f4add(acc1, bias1);
    o0.x = fminf(fmaxf(o0.x, -10.f), 10.f);
    o0.y = fminf(fmaxf(o0.y, -10.f), 10.f);
    o0.z = fminf(fmaxf(o0.z, -10.f), 10.f);
    o0.w = fminf(fmaxf(o0.w, -10.f), 10.f);
    o1.x = fminf(fmaxf(o1.x, -10.f), 10.f);
    o1.y = fminf(fmaxf(o1.y, -10.f), 10.f);
    o1.z = fminf(fmaxf(o1.z, -10.f), 10.f);
    o1.w = fminf(fmaxf(o1.w, -10.f), 10.f);

    // Coalesced: warp writes 1024 contiguous bytes
    float4* dst = (float4*)(out + 8 * (size_t)i);
    dst[0] = o0;
    dst[1] = o1;
}

extern "C" void kernel_launch(void* const* d_in, const int* in_sizes, int n_in,
                              void* d_out, int out_size)
{
    const float* coords = (const float*)d_in[0];
    const float* pxy    = (const float*)d_in[1];
    const float* pxz    = (const float*)d_in[2];
    const float* pyz    = (const float*)d_in[3];
    const float* projw  = (const float*)d_in[4];
    const float* projb  = (const float*)d_in[5];
    float* out = (float*)d_out;

    int N = in_sizes[0] / 3;

    // Prolog: fold projection into the planes (12 -> 8 channels)
    dim3 pgrid(RES * RES / 256, 3);
    project_planes_kernel<<<pgrid, 256>>>(pxy, pxz, pyz, projw);

    // Main gather kernel
    int blocks = (N + 255) / 256;
    geo_encoder_kernel<<<blocks, 256>>>(coords, projb, out, N);
}

// round 2
// speedup vs baseline: 1.7219x; 1.7219x over previous
#include <cuda_runtime.h>
#include <cuda_fp16.h>
#include <cuda_bf16.h>

#define RES   256
#define RANK  12
#define OUTC  8

// Projected planes in fp16: [plane][texel] = 8 ch * 2B = 16B per texel.
// 3 * 65536 * 16B = 3 MB scratch. uint4 for 16B-aligned single-load access.
__device__ uint4 g_planes_h[3][RES * RES];

// ---------------------------------------------------------------------------
// Prolog: project 12 -> 8 channels via the matching slice of proj_w and store
// as fp16. Runs every replay (deterministic, graph-capturable).
// ---------------------------------------------------------------------------
__global__ void project_planes_kernel(const float* __restrict__ pxy,
                                      const float* __restrict__ pxz,
                                      const float* __restrict__ pyz,
                                      const float* __restrict__ W)
{
    const int p = blockIdx.y;
    const float* __restrict__ src = (p == 0) ? pxy : ((p == 1) ? pxz : pyz);

    __shared__ float w[OUTC][RANK];
    int t = threadIdx.x;
    if (t < OUTC * RANK) {
        int o = t / RANK;
        int k = t % RANK;
        w[o][k] = W[o * (3 * RANK) + p * RANK + k];
    }
    __syncthreads();

    int texel = blockIdx.x * blockDim.x + threadIdx.x;   // 0 .. 65535
    const float* __restrict__ in = src + (size_t)texel * RANK;

    float f[RANK];
    float4 i0 = __ldg((const float4*)(in));
    float4 i1 = __ldg((const float4*)(in + 4));
    float4 i2 = __ldg((const float4*)(in + 8));
    f[0]=i0.x; f[1]=i0.y; f[2]=i0.z; f[3]=i0.w;
    f[4]=i1.x; f[5]=i1.y; f[6]=i1.z; f[7]=i1.w;
    f[8]=i2.x; f[9]=i2.y; f[10]=i2.z; f[11]=i2.w;

    float o[OUTC];
    #pragma unroll
    for (int c = 0; c < OUTC; c++) {
        float s = 0.f;
        #pragma unroll
        for (int k = 0; k < RANK; k++) s = fmaf(f[k], w[c][k], s);
        o[c] = s;
    }

    __half2 h0 = __floats2half2_rn(o[0], o[1]);
    __half2 h1 = __floats2half2_rn(o[2], o[3]);
    __half2 h2 = __floats2half2_rn(o[4], o[5]);
    __half2 h3 = __floats2half2_rn(o[6], o[7]);
    uint4 packed;
    packed.x = *(unsigned int*)&h0;
    packed.y = *(unsigned int*)&h1;
    packed.z = *(unsigned int*)&h2;
    packed.w = *(unsigned int*)&h3;
    g_planes_h[p][texel] = packed;
}

// ---------------------------------------------------------------------------
// Main kernel
// ---------------------------------------------------------------------------
struct F8 { float2 a, b, c, d; };  // 8 floats as 4 float2

__device__ __forceinline__ F8 unpack(uint4 u) {
    F8 r;
    r.a = __half22float2(*(__half2*)&u.x);
    r.b = __half22float2(*(__half2*)&u.y);
    r.c = __half22float2(*(__half2*)&u.z);
    r.d = __half22float2(*(__half2*)&u.w);
    return r;
}
__device__ __forceinline__ float2 lerp2(float2 a, float2 b, float w) {
    return make_float2(fmaf(w, b.x - a.x, a.x), fmaf(w, b.y - a.y, a.y));
}
__device__ __forceinline__ F8 lerp8(F8 a, F8 b, float w) {
    F8 r;
    r.a = lerp2(a.a, b.a, w);
    r.b = lerp2(a.b, b.b, w);
    r.c = lerp2(a.c, b.c, w);
    r.d = lerp2(a.d, b.d, w);
    return r;
}
__device__ __forceinline__ void accum8(F8& acc, F8 v) {
    acc.a.x += v.a.x; acc.a.y += v.a.y;
    acc.b.x += v.b.x; acc.b.y += v.b.y;
    acc.c.x += v.c.x; acc.c.y += v.c.y;
    acc.d.x += v.d.x; acc.d.y += v.d.y;
}

__device__ __forceinline__ void sample_accum(const uint4* __restrict__ plane,
                                             float cx, float cy, F8& acc)
{
    // unnormalize (align_corners=False) + border clamp; subsumes coord clip
    float ix = fminf(fmaxf(fmaf(cx, 128.f, 127.5f), 0.f), 255.f);
    float iy = fminf(fmaxf(fmaf(cy, 128.f, 127.5f), 0.f), 255.f);
    float x0f = floorf(ix);
    float y0f = floorf(iy);
    float wx = ix - x0f;
    float wy = iy - y0f;
    int x0 = (int)x0f;
    int y0 = (int)y0f;
    int dx = (x0 < RES - 1) ? 1   : 0;
    int dy = (y0 < RES - 1) ? RES : 0;

    const uint4* p00 = plane + (y0 * RES + x0);
    uint4 u00 = __ldg(p00);
    uint4 u01 = __ldg(p00 + dx);
    uint4 u10 = __ldg(p00 + dy);
    uint4 u11 = __ldg(p00 + dy + dx);

    F8 v00 = unpack(u00);
    F8 v01 = unpack(u01);
    F8 v10 = unpack(u10);
    F8 v11 = unpack(u11);

    F8 top = lerp8(v00, v01, wx);
    F8 bot = lerp8(v10, v11, wx);
    F8 res = lerp8(top, bot, wy);
    accum8(acc, res);
}

__global__ void __launch_bounds__(256)
geo_encoder_kernel(const float* __restrict__ coords,
                   const float* __restrict__ proj_b,
                   float* __restrict__ out,
                   int N)
{
    int i = blockIdx.x * blockDim.x + threadIdx.x;
    if (i >= N) return;

    float cx = coords[3 * (size_t)i + 0];
    float cy = coords[3 * (size_t)i + 1];
    float cz = coords[3 * (size_t)i + 2];

    F8 acc;
    acc.a = make_float2(0.f, 0.f);
    acc.b = make_float2(0.f, 0.f);
    acc.c = make_float2(0.f, 0.f);
    acc.d = make_float2(0.f, 0.f);

    sample_accum(g_planes_h[0], cx, cy, acc);  // xy: x=c0 (W), y=c1 (H)
    sample_accum(g_planes_h[1], cx, cz, acc);  // xz
    sample_accum(g_planes_h[2], cy, cz, acc);  // yz

    float4 bias0 = __ldg((const float4*)proj_b);
    float4 bias1 = __ldg((const float4*)(proj_b + 4));

    float o0 = acc.a.x + bias0.x;
    float o1 = acc.a.y + bias0.y;
    float o2 = acc.b.x + bias0.z;
    float o3 = acc.b.y + bias0.w;
    float o4 = acc.c.x + bias1.x;
    float o5 = acc.c.y + bias1.y;
    float o6 = acc.d.x + bias1.z;
    float o7 = acc.d.y + bias1.w;

    o0 = fminf(fmaxf(o0, -10.f), 10.f);
    o1 = fminf(fmaxf(o1, -10.f), 10.f);
    o2 = fminf(fmaxf(o2, -10.f), 10.f);
    o3 = fminf(fmaxf(o3, -10.f), 10.f);
    o4 = fminf(fmaxf(o4, -10.f), 10.f);
    o5 = fminf(fmaxf(o5, -10.f), 10.f);
    o6 = fminf(fmaxf(o6, -10.f), 10.f);
    o7 = fminf(fmaxf(o7, -10.f), 10.f);

    float4* dst = (float4*)(out + 8 * (size_t)i);
    dst[0] = make_float4(o0, o1, o2, o3);
    dst[1] = make_float4(o4, o5, o6, o7);
}

extern "C" void kernel_launch(void* const* d_in, const int* in_sizes, int n_in,
                              void* d_out, int out_size)
{
    const float* coords = (const float*)d_in[0];
    const float* pxy    = (const float*)d_in[1];
    const float* pxz    = (const float*)d_in[2];
    const float* pyz    = (const float*)d_in[3];
    const float* projw  = (const float*)d_in[4];
    const float* projb  = (const float*)d_in[5];
    float* out = (float*)d_out;

    int N = in_sizes[0] / 3;

    dim3 pgrid(RES * RES / 256, 3);
    project_planes_kernel<<<pgrid, 256>>>(pxy, pxz, pyz, projw);

    int blocks = (N + 255) / 256;
    geo_encoder_kernel<<<blocks, 256>>>(coords, projb, out, N);
}

// round 3
// speedup vs baseline: 2.2985x; 1.3348x over previous
#include <cuda_runtime.h>
#include <cuda_fp16.h>
#include <cuda_bf16.h>

#define RES   256
#define RANK  12
#define OUTC  8

// Projected planes in fp16: [plane][texel] = 8 ch * 2B = 16B per texel. 3 MB.
__device__ uint4 g_planes_h[3][RES * RES];

// ---------------------------------------------------------------------------
// Prolog: project 12 -> 8 channels via proj_w slice, store fp16.
// ---------------------------------------------------------------------------
__global__ void project_planes_kernel(const float* __restrict__ pxy,
                                      const float* __restrict__ pxz,
                                      const float* __restrict__ pyz,
                                      const float* __restrict__ W)
{
    const int p = blockIdx.y;
    const float* __restrict__ src = (p == 0) ? pxy : ((p == 1) ? pxz : pyz);

    __shared__ float w[OUTC][RANK];
    int t = threadIdx.x;
    if (t < OUTC * RANK) {
        int o = t / RANK;
        int k = t % RANK;
        w[o][k] = W[o * (3 * RANK) + p * RANK + k];
    }
    __syncthreads();

    int texel = blockIdx.x * blockDim.x + threadIdx.x;   // 0 .. 65535
    const float* __restrict__ in = src + (size_t)texel * RANK;

    float f[RANK];
    float4 i0 = __ldg((const float4*)(in));
    float4 i1 = __ldg((const float4*)(in + 4));
    float4 i2 = __ldg((const float4*)(in + 8));
    f[0]=i0.x; f[1]=i0.y; f[2]=i0.z; f[3]=i0.w;
    f[4]=i1.x; f[5]=i1.y; f[6]=i1.z; f[7]=i1.w;
    f[8]=i2.x; f[9]=i2.y; f[10]=i2.z; f[11]=i2.w;

    float o[OUTC];
    #pragma unroll
    for (int c = 0; c < OUTC; c++) {
        float s = 0.f;
        #pragma unroll
        for (int k = 0; k < RANK; k++) s = fmaf(f[k], w[c][k], s);
        o[c] = s;
    }

    __half2 h0 = __floats2half2_rn(o[0], o[1]);
    __half2 h1 = __floats2half2_rn(o[2], o[3]);
    __half2 h2 = __floats2half2_rn(o[4], o[5]);
    __half2 h3 = __floats2half2_rn(o[6], o[7]);
    uint4 packed;
    packed.x = *(unsigned int*)&h0;
    packed.y = *(unsigned int*)&h1;
    packed.z = *(unsigned int*)&h2;
    packed.w = *(unsigned int*)&h3;
    g_planes_h[p][texel] = packed;
}

// ---------------------------------------------------------------------------
// Main kernel: 2 lanes per point. Even lane = left column (x0), odd lane =
// right column (x1). Pair's addresses are adjacent 16B -> one L1 wavefront
// per point-row instead of two.
// ---------------------------------------------------------------------------
__device__ __forceinline__ void sample_col_accum(const uint4* __restrict__ plane,
                                                 float cx, float cy, int side,
                                                 float acc[8])
{
    // unnormalize (align_corners=False) + border clamp; subsumes coord clip
    float ix = fminf(fmaxf(fmaf(cx, 128.f, 127.5f), 0.f), 255.f);
    float iy = fminf(fmaxf(fmaf(cy, 128.f, 127.5f), 0.f), 255.f);
    float x0f = floorf(ix);
    float y0f = floorf(iy);
    float wx = ix - x0f;
    float wy = iy - y0f;
    int x0 = (int)x0f;
    int y0 = (int)y0f;

    int xs = x0 + ((x0 < RES - 1) ? side : 0);   // this lane's column
    int dy = (y0 < RES - 1) ? RES : 0;

    const uint4* p = plane + (y0 * RES + xs);
    uint4 ut = __ldg(p);        // top texel of this column
    uint4 ub = __ldg(p + dy);   // bottom texel

    float ws = side ? wx : (1.f - wx);   // horizontal weight for this column

    float2 t0 = __half22float2(*(__half2*)&ut.x);
    float2 t1 = __half22float2(*(__half2*)&ut.y);
    float2 t2 = __half22float2(*(__half2*)&ut.z);
    float2 t3 = __half22float2(*(__half2*)&ut.w);
    float2 b0 = __half22float2(*(__half2*)&ub.x);
    float2 b1 = __half22float2(*(__half2*)&ub.y);
    float2 b2 = __half22float2(*(__half2*)&ub.z);
    float2 b3 = __half22float2(*(__half2*)&ub.w);

    // col = top + wy*(bot-top), acc += ws * col
    acc[0] = fmaf(ws, fmaf(wy, b0.x - t0.x, t0.x), acc[0]);
    acc[1] = fmaf(ws, fmaf(wy, b0.y - t0.y, t0.y), acc[1]);
    acc[2] = fmaf(ws, fmaf(wy, b1.x - t1.x, t1.x), acc[2]);
    acc[3] = fmaf(ws, fmaf(wy, b1.y - t1.y, t1.y), acc[3]);
    acc[4] = fmaf(ws, fmaf(wy, b2.x - t2.x, t2.x), acc[4]);
    acc[5] = fmaf(ws, fmaf(wy, b2.y - t2.y, t2.y), acc[5]);
    acc[6] = fmaf(ws, fmaf(wy, b3.x - t3.x, t3.x), acc[6]);
    acc[7] = fmaf(ws, fmaf(wy, b3.y - t3.y, t3.y), acc[7]);
}

__global__ void __launch_bounds__(256)
geo_encoder_kernel(const float* __restrict__ coords,
                   const float* __restrict__ proj_b,
                   float* __restrict__ out,
                   int N)
{
    int t = blockIdx.x * blockDim.x + threadIdx.x;
    int i = t >> 1;          // point index
    if (i >= N) return;
    int side = t & 1;        // 0 = left column, 1 = right column

    // both lanes of a pair read the same coords (same line -> broadcast)
    float cx = coords[3 * (size_t)i + 0];
    float cy = coords[3 * (size_t)i + 1];
    float cz = coords[3 * (size_t)i + 2];

    float acc[8] = {0.f, 0.f, 0.f, 0.f, 0.f, 0.f, 0.f, 0.f};

    sample_col_accum(g_planes_h[0], cx, cy, side, acc);  // xy: x=c0 (W), y=c1 (H)
    sample_col_accum(g_planes_h[1], cx, cz, side, acc);  // xz
    sample_col_accum(g_planes_h[2], cy, cz, side, acc);  // yz

    // pair reduction: left-column + right-column contributions
    #pragma unroll
    for (int c = 0; c < 8; c++)
        acc[c] += __shfl_xor_sync(0xffffffffu, acc[c], 1);

    // this lane writes its own 16B half of the 32B output record
    float4 bias = __ldg((const float4*)proj_b + side);
    int base = side * 4;
    float o0 = fminf(fmaxf(acc[base + 0] + bias.x, -10.f), 10.f);
    float o1 = fminf(fmaxf(acc[base + 1] + bias.y, -10.f), 10.f);
    float o2 = fminf(fmaxf(acc[base + 2] + bias.z, -10.f), 10.f);
    float o3 = fminf(fmaxf(acc[base + 3] + bias.w, -10.f), 10.f);

    ((float4*)(out + 8 * (size_t)i))[side] = make_float4(o0, o1, o2, o3);
}

extern "C" void kernel_launch(void* const* d_in, const int* in_sizes, int n_in,
                              void* d_out, int out_size)
{
    const float* coords = (const float*)d_in[0];
    const float* pxy    = (const float*)d_in[1];
    const float* pxz    = (const float*)d_in[2];
    const float* pyz    = (const float*)d_in[3];
    const float* projw  = (const float*)d_in[4];
    const float* projb  = (const float*)d_in[5];
    float* out = (float*)d_out;

    int N = in_sizes[0] / 3;

    dim3 pgrid(RES * RES / 256, 3);
    project_planes_kernel<<<pgrid, 256>>>(pxy, pxz, pyz, projw);

    long long threads = 2LL * N;
    int blocks = (int)((threads + 255) / 256);
    geo_encoder_kernel<<<blocks, 256>>>(coords, projb, out, N);
}